// round 10
// baseline (speedup 1.0000x reference)
#include <cuda_runtime.h>
#include <math.h>

// ---------------------------------------------------------------------------
// Conv weights in __constant__ memory (warp-uniform indices -> uniform-path
// operand for FFMA; R9 measured fma=55.1% > the 50% 3-reg ceiling).
// Sizes: w1=768, w2=2304, w3=3072, w4=5120, w5=2025 -> total 13289 floats.
// ---------------------------------------------------------------------------
__constant__ float c_w[13289];

// ---------------------------------------------------------------------------
// Scratch (no allocations allowed -> static __device__ arrays)
// ---------------------------------------------------------------------------
__device__ float g_h1[256 * 3 * 50625];  // [B,3,15,15,15,15]
__device__ float g_h2[256 * 3 * 20736];  // [B,3,12,12,12,12]
__device__ float g_h3[256 * 4 * 6561];   // [B,4,9,9,9,9]
__device__ float g_h4[256 * 5 * 1296];   // [B,5,6,6,6,6]
__device__ float g_h5[256 * 5 * 256];    // [B,5,4,4,4,4] == [B,1280]

// ---------------------------------------------------------------------------
// 4D conv + bias + relu (valid, stride 1). R9 structure + NS multi-slice.
//   in : [B, CIN, S, S, S, S]; weights at c_w[WOFF..]; out: [B,COUT,T,...]
// Block = NS slices, slice = one (b, ow). Per ci: stage NS slabs into smem
// (z-rows padded to odd stride -> conflict-free LDS across oy lanes).
// Thread = (slice, ox, oy); accumulates all COUT x T outputs in registers.
// Weights read straight from __constant__ with warp-uniform indices.
// ---------------------------------------------------------------------------
template <int S, int K, int CIN, int COUT, int WOFF, int NS, int BLK>
__global__ void __launch_bounds__(BLK)
conv4d_relu(const float* __restrict__ x,
            const float* __restrict__ bias,
            float* __restrict__ y)
{
    constexpr int T    = S - K + 1;
    constexpr int TT   = T * T;
    constexpr int RS   = (S & 1) ? S : S + 1;   // padded z-row stride (odd)
    constexpr int S3   = S * S * S;
    constexpr int SLAB = K * S * S * RS;        // floats per slice slab
    constexpr int CK4  = CIN * K * K * K * K;

    extern __shared__ float slab0[];            // [NS * SLAB]

    const int tid = threadIdx.x;

    const int s   = tid / TT;
    const int rr  = tid - s * TT;
    const int ox  = rr / T;
    const int oy  = rr - ox * T;
    const bool active = (tid < NS * TT);
    const int slice = blockIdx.x * NS + s;
    const int b_t   = slice / T;
    const int ow_t  = slice % T;
    const float* slab = slab0 + s * SLAB;

    float acc[COUT][T];
#pragma unroll
    for (int co = 0; co < COUT; ++co)
#pragma unroll
        for (int oz = 0; oz < T; ++oz) acc[co][oz] = 0.f;

    for (int ci = 0; ci < CIN; ++ci) {
        __syncthreads();   // protect slabs from previous iteration's readers
        for (int i = tid; i < NS * K * S3; i += BLK) {
            int ss = i / (K * S3);
            int r  = i - ss * (K * S3);
            int sl = blockIdx.x * NS + ss;
            int bb = sl / T, oww = sl % T;
            int kw = r / S3;
            int r1 = r - kw * S3;
            int xx = r1 / (S * S);
            int r2 = r1 - xx * (S * S);
            int yy = r2 / S;
            int zz = r2 - yy * S;
            slab0[ss * SLAB + ((kw * S + xx) * S + yy) * RS + zz] =
                x[((size_t)(bb * CIN + ci) * S + oww) * S3 + r];
        }
        __syncthreads();

        if (active) {
#pragma unroll 1
            for (int kw = 0; kw < K; ++kw)
#pragma unroll 1
            for (int kx = 0; kx < K; ++kx)
#pragma unroll 1
            for (int ky = 0; ky < K; ++ky) {
                const float* row = &slab[((kw * S + ox + kx) * S + oy + ky) * RS];
                float r[S];
#pragma unroll
                for (int z = 0; z < S; ++z) r[z] = row[z];

                // weight base for this (ci,kw,kx,ky): warp-uniform
                const int wb = WOFF + ((ci * K + kw) * K + kx) * K * K + ky * K;

#pragma unroll
                for (int oz = 0; oz < T; ++oz)
#pragma unroll
                    for (int co = 0; co < COUT; ++co)
#pragma unroll
                        for (int kz = 0; kz < K; ++kz)
                            acc[co][oz] = fmaf(r[oz + kz],
                                               c_w[wb + co * CK4 + kz],
                                               acc[co][oz]);
            }
        }
    }

    if (active) {
#pragma unroll
        for (int co = 0; co < COUT; ++co) {
            float bv = bias[co];
#pragma unroll
            for (int oz = 0; oz < T; ++oz) {
                float v = acc[co][oz] + bv;
                y[((((((size_t)b_t * COUT + co) * T + ow_t) * T + ox) * T + oy) * T) + oz] =
                    v > 0.f ? v : 0.f;
            }
        }
    }
}

// ---------------------------------------------------------------------------
// Dense head: relu(h @ dw1.T + db1) @ dw2.T + db2 -> softmax over 2 classes.
// ---------------------------------------------------------------------------
__global__ void dense_head(const float* __restrict__ h,
                           const float* __restrict__ dw1,
                           const float* __restrict__ db1,
                           const float* __restrict__ dw2,
                           const float* __restrict__ db2,
                           float* __restrict__ out)
{
    __shared__ float hb[1280];
    __shared__ float a[33];
    const int b   = blockIdx.x;
    const int tid = threadIdx.x;

    for (int i = tid; i < 1280; i += blockDim.x) hb[i] = h[b * 1280 + i];
    __syncthreads();

    const int warp = tid >> 5, lane = tid & 31;
    const int nwarps = blockDim.x >> 5;
    for (int co = warp; co < 33; co += nwarps) {
        float s = 0.f;
        for (int i = lane; i < 1280; i += 32) s += hb[i] * dw1[co * 1280 + i];
#pragma unroll
        for (int o = 16; o > 0; o >>= 1) s += __shfl_down_sync(0xffffffffu, s, o);
        if (lane == 0) {
            float v = s + db1[co];
            a[co] = v > 0.f ? v : 0.f;
        }
    }
    __syncthreads();

    if (tid == 0) {
        float z0 = db2[0], z1 = db2[1];
#pragma unroll
        for (int i = 0; i < 33; ++i) {
            z0 += a[i] * dw2[i];
            z1 += a[i] * dw2[33 + i];
        }
        float m  = fmaxf(z0, z1);
        float e0 = expf(z0 - m), e1 = expf(z1 - m);
        float inv = 1.f / (e0 + e1);
        out[2 * b]     = e0 * inv;
        out[2 * b + 1] = e1 * inv;
    }
}

// ---------------------------------------------------------------------------
// Launch
// ---------------------------------------------------------------------------
extern "C" void kernel_launch(void* const* d_in, const int* in_sizes, int n_in,
                              void* d_out, int out_size)
{
    const float* x   = (const float*)d_in[0];
    const float* w1  = (const float*)d_in[1];
    const float* b1  = (const float*)d_in[2];
    const float* w2  = (const float*)d_in[3];
    const float* b2  = (const float*)d_in[4];
    const float* w3  = (const float*)d_in[5];
    const float* b3  = (const float*)d_in[6];
    const float* w4  = (const float*)d_in[7];
    const float* b4  = (const float*)d_in[8];
    const float* w5  = (const float*)d_in[9];
    const float* b5  = (const float*)d_in[10];
    const float* dw1 = (const float*)d_in[11];
    const float* db1 = (const float*)d_in[12];
    const float* dw2 = (const float*)d_in[13];
    const float* db2 = (const float*)d_in[14];
    float* out = (float*)d_out;

    float *h1, *h2, *h3, *h4, *h5;
    cudaGetSymbolAddress((void**)&h1, g_h1);
    cudaGetSymbolAddress((void**)&h2, g_h2);
    cudaGetSymbolAddress((void**)&h3, g_h3);
    cudaGetSymbolAddress((void**)&h4, g_h4);
    cudaGetSymbolAddress((void**)&h5, g_h5);

    // Copy conv weights into constant memory (D2D async, graph-capturable).
    // Offsets: w1=0(768), w2=768(2304), w3=3072(3072), w4=6144(5120), w5=11264(2025)
    cudaMemcpyToSymbolAsync(c_w, w1,  768 * 4,     0 * 4, cudaMemcpyDeviceToDevice, 0);
    cudaMemcpyToSymbolAsync(c_w, w2, 2304 * 4,   768 * 4, cudaMemcpyDeviceToDevice, 0);
    cudaMemcpyToSymbolAsync(c_w, w3, 3072 * 4,  3072 * 4, cudaMemcpyDeviceToDevice, 0);
    cudaMemcpyToSymbolAsync(c_w, w4, 5120 * 4,  6144 * 4, cudaMemcpyDeviceToDevice, 0);
    cudaMemcpyToSymbolAsync(c_w, w5, 2025 * 4, 11264 * 4, cudaMemcpyDeviceToDevice, 0);

    // Active-lane fractions: L1 225/256, L2 288/288, L3 243/256, L4 216/224,
    // L5 128/128. Slab smem (floats): L1 24624, L2 13500, L3 7488, L4 2916, L5 756.
    constexpr int sm1 = 1 * 4 * 18 * 18 * 19 * 4;  //  98,496
    constexpr int sm2 = 2 * 4 * 15 * 15 * 15 * 4;  // 108,000
    constexpr int sm3 = 3 * 4 * 12 * 12 * 13 * 4;  //  89,856
    constexpr int sm4 = 6 * 4 * 9 * 9 * 9 * 4;     //  69,984
    constexpr int sm5 = 8 * 3 * 6 * 6 * 7 * 4;     //  24,192

    cudaFuncSetAttribute((conv4d_relu<18, 4, 1, 3, 0, 1, 256>),
                         cudaFuncAttributeMaxDynamicSharedMemorySize, sm1);
    cudaFuncSetAttribute((conv4d_relu<15, 4, 3, 3, 768, 2, 288>),
                         cudaFuncAttributeMaxDynamicSharedMemorySize, sm2);
    cudaFuncSetAttribute((conv4d_relu<12, 4, 3, 4, 3072, 3, 256>),
                         cudaFuncAttributeMaxDynamicSharedMemorySize, sm3);
    cudaFuncSetAttribute((conv4d_relu<9, 4, 4, 5, 6144, 6, 224>),
                         cudaFuncAttributeMaxDynamicSharedMemorySize, sm4);

    conv4d_relu<18, 4, 1, 3, 0, 1, 256>    <<<256 * 15,     256, sm1>>>(x,  b1, h1);
    conv4d_relu<15, 4, 3, 3, 768, 2, 288>  <<<256 * 12 / 2, 288, sm2>>>(h1, b2, h2);
    conv4d_relu<12, 4, 3, 4, 3072, 3, 256> <<<256 * 9 / 3,  256, sm3>>>(h2, b3, h3);
    conv4d_relu< 9, 4, 4, 5, 6144, 6, 224> <<<256 * 6 / 6,  224, sm4>>>(h3, b4, h4);
    conv4d_relu< 6, 3, 5, 5, 11264, 8, 128><<<256 * 4 / 8,  128, sm5>>>(h4, b5, h5);
    dense_head<<<256, 256>>>(h5, dw1, db1, dw2, db2, out);
}

// round 12
// speedup vs baseline: 1.4435x; 1.4435x over previous
#include <cuda_runtime.h>
#include <math.h>

// ---------------------------------------------------------------------------
// Conv weights in __constant__ memory (R9 win: const-operand FFMA beats the
// 3-reg rt=2 ceiling; measured fma=55.1% > 50%).
// ---------------------------------------------------------------------------
__constant__ float c_w[13289];

// ---------------------------------------------------------------------------
// Scratch (no allocations allowed -> static __device__ arrays)
// ---------------------------------------------------------------------------
__device__ float g_h1[256 * 3 * 50625];  // [B,3,15,15,15,15]
__device__ float g_h2[256 * 3 * 20736];  // [B,3,12,12,12,12]
__device__ float g_h3[256 * 4 * 6561];   // [B,4,9,9,9,9]
__device__ float g_h4[256 * 5 * 1296];   // [B,5,6,6,6,6]
__device__ float g_h5[256 * 5 * 256];    // [B,5,4,4,4,4] == [B,1280]

// z-row stride: even (8B-aligned pair loads) with odd half (conflict-free
// LDS.64 across oy lanes). 18->18, 15->18, 12->14, 9->10, 6->6.
__host__ __device__ constexpr int rs2_of(int S) {
    int e = (S + 1) & ~1;
    return ((e / 2) & 1) ? e : e + 2;
}

// ---------------------------------------------------------------------------
// 4D conv + bias + relu. Overlap-sliced slab: block covers NS CONTIGUOUS ow
// positions of one batch -> stages K+NS-1 w-slices (shared, not NS*K).
// Thread = (slice, oz-chunk, ox, oy); acc[COUT][OZB] in registers.
// Row values loaded as float2 (LDS.64); weights from __constant__ (uniform).
// Thread budget: BLK >= NS * ZSPL * T * T (checked statically).
// ---------------------------------------------------------------------------
template <int S, int K, int CIN, int COUT, int WOFF, int NS, int ZSPL,
          int BLK, int MINB>
__global__ void __launch_bounds__(BLK, MINB)
conv4d_relu(const float* __restrict__ x,
            const float* __restrict__ bias,
            float* __restrict__ y)
{
    constexpr int T    = S - K + 1;
    constexpr int TT   = T * T;
    constexpr int OZB  = (T + ZSPL - 1) / ZSPL;   // oz per chunk
    constexpr int RS   = rs2_of(S);
    constexpr int S3   = S * S * S;
    constexpr int NW   = K + NS - 1;              // staged w-slices
    constexpr int SLAB = NW * S * S * RS + 8;     // +pad for tail over-read
    constexpr int CK4  = CIN * K * K * K * K;
    constexpr int WIN  = OZB + K - 1;             // row floats needed
    constexpr int NR2  = (WIN + 1) / 2;           // float2 loads per row
    constexpr int GRP  = T / NS;                  // ow groups per batch
    constexpr int PERS = ZSPL * TT;

    static_assert(T % NS == 0, "NS must divide T");
    static_assert(ZSPL == 1 || (OZB % 2) == 0, "oz chunks must start even");
    static_assert(NS * PERS <= BLK, "thread budget too small");

    extern __shared__ float slab[];               // [SLAB]

    const int tid = threadIdx.x;
    const int b   = blockIdx.x / GRP;
    const int ow0 = (blockIdx.x - b * GRP) * NS;

    const int s   = tid / PERS;
    const int r0  = tid - s * PERS;
    const int zc  = r0 / TT;
    const int rr  = r0 - zc * TT;
    const int ox  = rr / T;
    const int oy  = rr - ox * T;
    const int oz0 = zc * OZB;                     // even by construction
    const bool active = (tid < NS * PERS);

    float acc[COUT][OZB];
#pragma unroll
    for (int co = 0; co < COUT; ++co)
#pragma unroll
        for (int oz = 0; oz < OZB; ++oz) acc[co][oz] = 0.f;

    for (int ci = 0; ci < CIN; ++ci) {
        __syncthreads();   // protect slab from previous iteration's readers
        const float* src = x + ((size_t)(b * CIN + ci) * S + ow0) * S3;
        for (int i = tid; i < NW * S3; i += BLK) {
            int kw = i / S3;
            int r1 = i - kw * S3;
            int xx = r1 / (S * S);
            int r2 = r1 - xx * (S * S);
            int yy = r2 / S;
            int zz = r2 - yy * S;
            slab[((kw * S + xx) * S + yy) * RS + zz] = src[i];
        }
        __syncthreads();

        if (active) {
#pragma unroll 1
            for (int kw = 0; kw < K; ++kw)
#pragma unroll 1
            for (int kx = 0; kx < K; ++kx)
#pragma unroll 1
            for (int ky = 0; ky < K; ++ky) {
                // slice s uses staged w-slice (s + kw); 8B-aligned row base
                const float* row =
                    &slab[(((s + kw) * S + ox + kx) * S + oy + ky) * RS + oz0];
                float r[2 * NR2];
#pragma unroll
                for (int j = 0; j < NR2; ++j) {
                    float2 v = reinterpret_cast<const float2*>(row)[j];
                    r[2 * j]     = v.x;
                    r[2 * j + 1] = v.y;
                }

                const int wb = WOFF + ((ci * K + kw) * K + kx) * K * K + ky * K;

#pragma unroll
                for (int oz = 0; oz < OZB; ++oz)
#pragma unroll
                    for (int co = 0; co < COUT; ++co)
#pragma unroll
                        for (int kz = 0; kz < K; ++kz)
                            acc[co][oz] = fmaf(r[oz + kz],
                                               c_w[wb + co * CK4 + kz],
                                               acc[co][oz]);
            }
        }
    }

    if (active) {
        const int ow_t = ow0 + s;
#pragma unroll
        for (int co = 0; co < COUT; ++co) {
            float bv = bias[co];
#pragma unroll
            for (int oz = 0; oz < OZB; ++oz) {
                if (oz0 + oz < T) {
                    float v = acc[co][oz] + bv;
                    y[((((((size_t)b * COUT + co) * T + ow_t) * T + ox) * T + oy) * T)
                      + oz0 + oz] = v > 0.f ? v : 0.f;
                }
            }
        }
    }
}

// ---------------------------------------------------------------------------
// Dense head: relu(h @ dw1.T + db1) @ dw2.T + db2 -> softmax over 2 classes.
// ---------------------------------------------------------------------------
__global__ void dense_head(const float* __restrict__ h,
                           const float* __restrict__ dw1,
                           const float* __restrict__ db1,
                           const float* __restrict__ dw2,
                           const float* __restrict__ db2,
                           float* __restrict__ out)
{
    __shared__ float hb[1280];
    __shared__ float a[33];
    const int b   = blockIdx.x;
    const int tid = threadIdx.x;

    for (int i = tid; i < 1280; i += blockDim.x) hb[i] = h[b * 1280 + i];
    __syncthreads();

    const int warp = tid >> 5, lane = tid & 31;
    const int nwarps = blockDim.x >> 5;
    for (int co = warp; co < 33; co += nwarps) {
        float s = 0.f;
        for (int i = lane; i < 1280; i += 32) s += hb[i] * dw1[co * 1280 + i];
#pragma unroll
        for (int o = 16; o > 0; o >>= 1) s += __shfl_down_sync(0xffffffffu, s, o);
        if (lane == 0) {
            float v = s + db1[co];
            a[co] = v > 0.f ? v : 0.f;
        }
    }
    __syncthreads();

    if (tid == 0) {
        float z0 = db2[0], z1 = db2[1];
#pragma unroll
        for (int i = 0; i < 33; ++i) {
            z0 += a[i] * dw2[i];
            z1 += a[i] * dw2[33 + i];
        }
        float m  = fmaxf(z0, z1);
        float e0 = expf(z0 - m), e1 = expf(z1 - m);
        float inv = 1.f / (e0 + e1);
        out[2 * b]     = e0 * inv;
        out[2 * b + 1] = e1 * inv;
    }
}

// ---------------------------------------------------------------------------
// Launch
// ---------------------------------------------------------------------------
extern "C" void kernel_launch(void* const* d_in, const int* in_sizes, int n_in,
                              void* d_out, int out_size)
{
    const float* x   = (const float*)d_in[0];
    const float* w1  = (const float*)d_in[1];
    const float* b1  = (const float*)d_in[2];
    const float* w2  = (const float*)d_in[3];
    const float* b2  = (const float*)d_in[4];
    const float* w3  = (const float*)d_in[5];
    const float* b3  = (const float*)d_in[6];
    const float* w4  = (const float*)d_in[7];
    const float* b4  = (const float*)d_in[8];
    const float* w5  = (const float*)d_in[9];
    const float* b5  = (const float*)d_in[10];
    const float* dw1 = (const float*)d_in[11];
    const float* db1 = (const float*)d_in[12];
    const float* dw2 = (const float*)d_in[13];
    const float* db2 = (const float*)d_in[14];
    float* out = (float*)d_out;

    float *h1, *h2, *h3, *h4, *h5;
    cudaGetSymbolAddress((void**)&h1, g_h1);
    cudaGetSymbolAddress((void**)&h2, g_h2);
    cudaGetSymbolAddress((void**)&h3, g_h3);
    cudaGetSymbolAddress((void**)&h4, g_h4);
    cudaGetSymbolAddress((void**)&h5, g_h5);

    // Conv weights -> constant memory (D2D async, graph-capturable).
    cudaMemcpyToSymbolAsync(c_w, w1,  768 * 4,     0 * 4, cudaMemcpyDeviceToDevice, 0);
    cudaMemcpyToSymbolAsync(c_w, w2, 2304 * 4,   768 * 4, cudaMemcpyDeviceToDevice, 0);
    cudaMemcpyToSymbolAsync(c_w, w3, 3072 * 4,  3072 * 4, cudaMemcpyDeviceToDevice, 0);
    cudaMemcpyToSymbolAsync(c_w, w4, 5120 * 4,  6144 * 4, cudaMemcpyDeviceToDevice, 0);
    cudaMemcpyToSymbolAsync(c_w, w5, 2025 * 4, 11264 * 4, cudaMemcpyDeviceToDevice, 0);

    // Thread budgets (NS*ZSPL*T*T <= BLK), all statically asserted:
    // L1: NS=1 ZSPL=2 -> 450 <= 480   RS=18 smem=(4*5832+8)*4= 93,344 -> 2 blk/SM
    // L2: NS=3 ZSPL=1 -> 432 <= 432   RS=18 smem=(6*4050+8)*4= 97,232 -> 2 blk/SM
    // L3: NS=3 ZSPL=1 -> 243 <= 256   RS=14 smem=(6*2016+8)*4= 48,416 -> 4 blk/SM
    // L4: NS=2 ZSPL=3 -> 216 <= 224   RS=10 smem=(5*810+8)*4 = 16,232 -> grid 768
    // L5: NS=2 ZSPL=2 -> 64  <= 64    RS=6  smem=(4*216+8)*4 =  3,488 -> grid 512
    constexpr int sm1 = (4 * 18 * 18 * 18 + 8) * 4;
    constexpr int sm2 = (6 * 15 * 15 * 18 + 8) * 4;
    constexpr int sm3 = (6 * 12 * 12 * 14 + 8) * 4;
    constexpr int sm4 = (5 * 9 * 9 * 10 + 8) * 4;
    constexpr int sm5 = (4 * 6 * 6 * 6 + 8) * 4;

    cudaFuncSetAttribute((conv4d_relu<18, 4, 1, 3, 0, 1, 2, 480, 2>),
                         cudaFuncAttributeMaxDynamicSharedMemorySize, sm1);
    cudaFuncSetAttribute((conv4d_relu<15, 4, 3, 3, 768, 3, 1, 432, 2>),
                         cudaFuncAttributeMaxDynamicSharedMemorySize, sm2);
    cudaFuncSetAttribute((conv4d_relu<12, 4, 3, 4, 3072, 3, 1, 256, 3>),
                         cudaFuncAttributeMaxDynamicSharedMemorySize, sm3);
    cudaFuncSetAttribute((conv4d_relu<9, 4, 4, 5, 6144, 2, 3, 224, 5>),
                         cudaFuncAttributeMaxDynamicSharedMemorySize, sm4);
    cudaFuncSetAttribute((conv4d_relu<6, 3, 5, 5, 11264, 2, 2, 64, 8>),
                         cudaFuncAttributeMaxDynamicSharedMemorySize, sm5);

    // grids: B * (T / NS)
    conv4d_relu<18, 4, 1, 3, 0, 1, 2, 480, 2>    <<<256 * 15, 480, sm1>>>(x,  b1, h1);
    conv4d_relu<15, 4, 3, 3, 768, 3, 1, 432, 2>  <<<256 * 4,  432, sm2>>>(h1, b2, h2);
    conv4d_relu<12, 4, 3, 4, 3072, 3, 1, 256, 3> <<<256 * 3,  256, sm3>>>(h2, b3, h3);
    conv4d_relu< 9, 4, 4, 5, 6144, 2, 3, 224, 5> <<<256 * 3,  224, sm4>>>(h3, b4, h4);
    conv4d_relu< 6, 3, 5, 5, 11264, 2, 2, 64, 8> <<<256 * 2,   64, sm5>>>(h4, b5, h5);
    dense_head<<<256, 256>>>(h5, dw1, db1, dw2, db2, out);
}